// round 8
// baseline (speedup 1.0000x reference)
#include <cuda_runtime.h>
#include <cstdint>

#define T_LEN 2048
#define B_SZ  2
#define EMB   512
#define ROWS  4096       // B*T
#define HEADS 8
#define HDIM  64
#define NHASH 2
#define FULLMASK 0xffffffffu

// ---------------------------------------------------------------------------
// Scratch
// ---------------------------------------------------------------------------
__device__ float g_Q[ROWS * EMB];
__device__ float g_K[ROWS * EMB];
__device__ float g_V[ROWS * EMB];
__device__ unsigned char g_qh[NHASH * B_SZ * HEADS * T_LEN];
__device__ unsigned char g_kh[NHASH * B_SZ * HEADS * T_LEN];
__device__ float g_att[NHASH][ROWS * EMB];
__device__ int g_qstart[32][65];
__device__ int g_kstart[32][65];
__device__ unsigned short g_qlist[32 * T_LEN];
__device__ unsigned short g_klist[32 * T_LEN];

// ---------------------------------------------------------------------------
// Packed fp32x2 FMA helper (kept from R6; GEMMs are at the FFMA issue floor
// either way and this version is the currently proven-correct one).
// ---------------------------------------------------------------------------
__device__ __forceinline__ float2 ffma2(float2 a, float2 b, float2 c)
{
    unsigned long long ua = *reinterpret_cast<unsigned long long*>(&a);
    unsigned long long ub = *reinterpret_cast<unsigned long long*>(&b);
    unsigned long long uc = *reinterpret_cast<unsigned long long*>(&c);
    unsigned long long ud;
    asm("fma.rn.f32x2 %0, %1, %2, %3;" : "=l"(ud) : "l"(ua), "l"(ub), "l"(uc));
    return *reinterpret_cast<float2*>(&ud);
}

#define AS2_STRIDE 258
#define BSX_STRIDE 132
#define QKV_SMEM ((2 * 16 * AS2_STRIDE + 2 * 16 * BSX_STRIDE) * 4)

__device__ __forceinline__ void tile_fma2(const float* __restrict__ A2,
                                          const float* __restrict__ Bx,
                                          float2 acc[8][4], int tx, int ty)
{
#pragma unroll
    for (int k = 0; k < 16; k++) {
        const float* ar = A2 + k * AS2_STRIDE;
        const float* br = Bx + k * BSX_STRIDE;
        float2 avd[8], bv2[4];
#pragma unroll
        for (int i = 0; i < 8; i++)
            avd[i] = *reinterpret_cast<const float2*>(ar + 2 * (ty * 8 + i));
#pragma unroll
        for (int p = 0; p < 4; p++)
            bv2[p] = *reinterpret_cast<const float2*>(br + p * 32 + tx * 2);
#pragma unroll
        for (int i = 0; i < 8; i++)
#pragma unroll
            for (int p = 0; p < 4; p++)
                acc[i][p] = ffma2(avd[i], bv2[p], acc[i][p]);
    }
}

// ---------------------------------------------------------------------------
// Kernel 1: fused QKV projection, double-buffered.
// ---------------------------------------------------------------------------
__global__ __launch_bounds__(256, 2) void gemm_qkv(
    const float* __restrict__ Xq, const float* __restrict__ Xk, const float* __restrict__ Xv,
    const float* __restrict__ Wq, const float* __restrict__ Wk, const float* __restrict__ Wv,
    const float* __restrict__ bq, const float* __restrict__ bk, const float* __restrict__ bv)
{
    extern __shared__ float sm[];
    float* A2 = sm;
    float* Bx = sm + 2 * 16 * AS2_STRIDE;

    const int tid = threadIdx.x;
    const int bn = blockIdx.x;
    const int bm = blockIdx.y;
    const int z  = blockIdx.z;
    const int tx = tid & 15, ty = tid >> 4;

    const float* X = (z == 0) ? Xq : (z == 1) ? Xk : Xv;
    const float* W = (z == 0) ? Wq : (z == 1) ? Wk : Wv;
    const float* bias = (z == 0) ? bq : (z == 1) ? bk : bv;
    float* outp = (z == 0) ? g_Q : (z == 1) ? g_K : g_V;

    const int rr = tid >> 1;
    const int kb = (tid & 1) * 8;
    const int r = bm * 128 + rr;
    const int src = (r & 1) * T_LEN + (r >> 1);
    const float* Aptr = X + (size_t)src * EMB + kb;
    const float* Bptr = W + (size_t)(bn * 128 + rr) * EMB + kb;

    float2 acc[8][4];
#pragma unroll
    for (int i = 0; i < 8; i++)
#pragma unroll
        for (int p = 0; p < 4; p++) acc[i][p] = make_float2(0.f, 0.f);

    float4 ra0 = *reinterpret_cast<const float4*>(Aptr);
    float4 ra1 = *reinterpret_cast<const float4*>(Aptr + 4);
    float4 rb0 = *reinterpret_cast<const float4*>(Bptr);
    float4 rb1 = *reinterpret_cast<const float4*>(Bptr + 4);

    {
        float va[8] = {ra0.x, ra0.y, ra0.z, ra0.w, ra1.x, ra1.y, ra1.z, ra1.w};
        float vb[8] = {rb0.x, rb0.y, rb0.z, rb0.w, rb1.x, rb1.y, rb1.z, rb1.w};
#pragma unroll
        for (int c = 0; c < 8; c++) {
            float* pa = A2 + (kb + c) * AS2_STRIDE + 2 * rr;
            pa[0] = va[c]; pa[1] = va[c];
            Bx[(kb + c) * BSX_STRIDE + rr] = vb[c];
        }
    }
    __syncthreads();

    const int NS = EMB / 16;
    for (int s = 0; s < NS; s++) {
        const int cur = s & 1;
        if (s + 1 < NS) {
            ra0 = *reinterpret_cast<const float4*>(Aptr + (s + 1) * 16);
            ra1 = *reinterpret_cast<const float4*>(Aptr + (s + 1) * 16 + 4);
            rb0 = *reinterpret_cast<const float4*>(Bptr + (s + 1) * 16);
            rb1 = *reinterpret_cast<const float4*>(Bptr + (s + 1) * 16 + 4);
        }
        tile_fma2(A2 + cur * 16 * AS2_STRIDE, Bx + cur * 16 * BSX_STRIDE, acc, tx, ty);
        if (s + 1 < NS) {
            __syncthreads();
            const int nxt = cur ^ 1;
            float va[8] = {ra0.x, ra0.y, ra0.z, ra0.w, ra1.x, ra1.y, ra1.z, ra1.w};
            float vb[8] = {rb0.x, rb0.y, rb0.z, rb0.w, rb1.x, rb1.y, rb1.z, rb1.w};
#pragma unroll
            for (int c = 0; c < 8; c++) {
                float* pa = A2 + (nxt * 16 + kb + c) * AS2_STRIDE + 2 * rr;
                pa[0] = va[c]; pa[1] = va[c];
                Bx[(nxt * 16 + kb + c) * BSX_STRIDE + rr] = vb[c];
            }
            __syncthreads();
        }
    }

    float2 bb2[4];
#pragma unroll
    for (int p = 0; p < 4; p++)
        bb2[p] = *reinterpret_cast<const float2*>(bias + bn * 128 + p * 32 + tx * 2);
#pragma unroll
    for (int i = 0; i < 8; i++) {
        int ro = bm * 128 + ty * 8 + i;
        float* op = outp + (size_t)ro * EMB + bn * 128;
#pragma unroll
        for (int p = 0; p < 4; p++) {
            float2 v = acc[i][p];
            v.x += bb2[p].x; v.y += bb2[p].y;
            *reinterpret_cast<float2*>(op + p * 32 + tx * 2) = v;
        }
    }
}

// ---------------------------------------------------------------------------
// Kernel 2: LSH hashing GEMM (64x128 tile) + fused argmax.
// ---------------------------------------------------------------------------
__global__ __launch_bounds__(256) void hash_gemm(const float* __restrict__ lshW,
                                                 const float* __restrict__ lshb)
{
    __shared__ float As2h[16][130];
    __shared__ float Bsh[16][132];
    const int tid = threadIdx.x;
    const int bm = blockIdx.x;
    const int tensor = blockIdx.y;
    const int tx = tid & 15, ty = tid >> 4;

    const float* A = tensor ? g_K : g_Q;
    unsigned char* dst = tensor ? g_kh : g_qh;

    float2 acc[4][4];
#pragma unroll
    for (int i = 0; i < 4; i++)
#pragma unroll
        for (int p = 0; p < 4; p++) acc[i][p] = make_float2(0.f, 0.f);

    for (int kk = 0; kk < 64; kk += 16) {
        {
            int arr = tid >> 2, ak4 = tid & 3;
            float4 a = *reinterpret_cast<const float4*>(A + (size_t)(bm * 64 + arr) * 64 + kk + ak4 * 4);
            float va[4] = {a.x, a.y, a.z, a.w};
#pragma unroll
            for (int c = 0; c < 4; c++) {
                As2h[ak4 * 4 + c][2 * arr] = va[c];
                As2h[ak4 * 4 + c][2 * arr + 1] = va[c];
            }
        }
#pragma unroll
        for (int i = 0; i < 2; i++) {
            int idx = tid * 2 + i;
            int rr = idx >> 2, bk4 = idx & 3;
            float4 b = *reinterpret_cast<const float4*>(lshW + (size_t)rr * 64 + kk + bk4 * 4);
            Bsh[bk4 * 4 + 0][rr] = b.x; Bsh[bk4 * 4 + 1][rr] = b.y;
            Bsh[bk4 * 4 + 2][rr] = b.z; Bsh[bk4 * 4 + 3][rr] = b.w;
        }
        __syncthreads();
#pragma unroll
        for (int k = 0; k < 16; k++) {
            float2 avd[4], bv2[4];
#pragma unroll
            for (int i = 0; i < 4; i++)
                avd[i] = *reinterpret_cast<const float2*>(&As2h[k][2 * (ty * 4 + i)]);
#pragma unroll
            for (int p = 0; p < 4; p++)
                bv2[p] = *reinterpret_cast<const float2*>(&Bsh[k][p * 32 + tx * 2]);
#pragma unroll
            for (int i = 0; i < 4; i++)
#pragma unroll
                for (int p = 0; p < 4; p++)
                    acc[i][p] = ffma2(avd[i], bv2[p], acc[i][p]);
        }
        __syncthreads();
    }

    float2 bb2[4];
#pragma unroll
    for (int p = 0; p < 4; p++)
        bb2[p] = *reinterpret_cast<const float2*>(lshb + p * 32 + tx * 2);

#pragma unroll
    for (int i = 0; i < 4; i++) {
        const int m  = bm * 64 + ty * 4 + i;
        const int r  = m >> 3, h = m & 7;
        const int nb = r >> 11, nt = r & 2047;
#pragma unroll
        for (int hh = 0; hh < 2; hh++) {
            float2 c0 = acc[i][2 * hh];
            float2 c1 = acc[i][2 * hh + 1];
            c0.x += bb2[2 * hh].x;     c0.y += bb2[2 * hh].y;
            c1.x += bb2[2 * hh + 1].x; c1.y += bb2[2 * hh + 1].y;
            float bvv = c0.x; int bi = tx * 2;
            if (c0.y > bvv) { bvv = c0.y; bi = tx * 2 + 1; }
            if (c1.x > bvv) { bvv = c1.x; bi = 32 + tx * 2; }
            if (c1.y > bvv) { bvv = c1.y; bi = 33 + tx * 2; }
#pragma unroll
            for (int off = 1; off < 16; off <<= 1) {
                float ov = __shfl_xor_sync(FULLMASK, bvv, off);
                int   oi = __shfl_xor_sync(FULLMASK, bi, off);
                if (ov > bvv || (ov == bvv && oi < bi)) { bvv = ov; bi = oi; }
            }
            if (tx == 0)
                dst[((hh * B_SZ + nb) * HEADS + h) * T_LEN + nt] = (unsigned char)bi;
        }
    }
}

// ---------------------------------------------------------------------------
// Kernel 3: bucketize
// ---------------------------------------------------------------------------
__global__ __launch_bounds__(256) void bucketize_kernel()
{
    __shared__ int cnt[2][64];
    __shared__ int off[2][64];
    const int combo = blockIdx.x;
    const int tid = threadIdx.x;

    for (int i = tid; i < 128; i += 256) cnt[i >> 6][i & 63] = 0;
    __syncthreads();

    const unsigned char* qh = g_qh + combo * T_LEN;
    const unsigned char* kh = g_kh + combo * T_LEN;
    for (int i = tid; i < T_LEN; i += 256) {
        atomicAdd(&cnt[0][qh[i]], 1);
        atomicAdd(&cnt[1][kh[i]], 1);
    }
    __syncthreads();

    if (tid == 0) {
        int s = 0;
        for (int j = 0; j < 64; j++) { g_qstart[combo][j] = s; off[0][j] = s; s += cnt[0][j]; }
        g_qstart[combo][64] = s;
    }
    if (tid == 32) {
        int s = 0;
        for (int j = 0; j < 64; j++) { g_kstart[combo][j] = s; off[1][j] = s; s += cnt[1][j]; }
        g_kstart[combo][64] = s;
    }
    __syncthreads();

    for (int i = tid; i < T_LEN; i += 256) {
        int p = atomicAdd(&off[0][qh[i]], 1);
        g_qlist[combo * T_LEN + p] = (unsigned short)i;
        p = atomicAdd(&off[1][kh[i]], 1);
        g_klist[combo * T_LEN + p] = (unsigned short)i;
    }
}

// ---------------------------------------------------------------------------
// Kernel 4: per-bucket flash attention with 32x32 tiles (bucket-size matched).
// grid = (64 buckets, 32 combos), 256 threads.
// Thread (tx=tid&15, ty=tid>>4): S fragment rows {ty*2,ty*2+1} x cols
// {tx*2,tx*2+1}; O fragment rows {ty*2,+1} x dims {tx*4..+3}.
// K staged transposed (stride 33) for conflict-free scalar reads.
// ---------------------------------------------------------------------------
#define QS 68   // q/v row stride (floats), 16B-aligned rows
#define KS 33   // transposed-K / P stride

__global__ __launch_bounds__(256) void attn_bucket_kernel()
{
    __shared__ float qsh[32 * QS];
    __shared__ float ksh[64 * KS];   // [k-dim][key]
    __shared__ float vsh[32 * QS];
    __shared__ float psh[32 * KS];   // [q-row][key]
    __shared__ int   qid[32];

    const int bucket = blockIdx.x;
    const int combo  = blockIdx.y;
    const int hash = combo >> 4;
    const int b    = (combo >> 3) & 1;
    const int h    = combo & 7;
    const int tid  = threadIdx.x;
    const int tx = tid & 15, ty = tid >> 4;

    const int qs = g_qstart[combo][bucket];
    const int nq = g_qstart[combo][bucket + 1] - qs;
    if (nq == 0) return;
    const int ks = g_kstart[combo][bucket];
    const int kn = g_kstart[combo][bucket + 1] - ks;

    const unsigned short* qlist = g_qlist + combo * T_LEN;
    const unsigned short* klist = g_klist + combo * T_LEN;

    float* Op = g_att[hash] + (size_t)b * T_LEN * EMB + h * HDIM;

    if (bucket >= 32 || kn == 0) {
        for (int idx = tid; idx < nq * 16; idx += 256) {
            int qi = idx >> 4, sl = idx & 15;
            int t = qlist[qs + qi];
            *reinterpret_cast<float4*>(Op + (size_t)t * EMB + sl * 4) =
                make_float4(0.f, 0.f, 0.f, 0.f);
        }
        return;
    }

    const float* Qp = g_Q + (size_t)b * T_LEN * EMB + h * HDIM;
    const float* Kp = g_K + (size_t)b * T_LEN * EMB + h * HDIM;
    const float* Vp = g_V + (size_t)b * T_LEN * EMB + h * HDIM;

    for (int q0 = 0; q0 < nq; q0 += 32) {
        const int cq = min(32, nq - q0);
        __syncthreads();
        // load Q tile: 32 rows x 16 float4 slots = 512 tasks
        for (int task = tid; task < 512; task += 256) {
            int row = task >> 4, slot = task & 15;
            if (row < cq) {
                int t = qlist[qs + q0 + row];
                if (slot == 0) qid[row] = t;
                float4 v4 = *reinterpret_cast<const float4*>(Qp + (size_t)t * EMB + slot * 4);
                float* d = &qsh[row * QS + slot * 4];
                d[0] = v4.x; d[1] = v4.y; d[2] = v4.z; d[3] = v4.w;
            }
        }
        __syncthreads();

        float m[2], l[2], o[2][4];
#pragma unroll
        for (int i = 0; i < 2; i++) {
            m[i] = -INFINITY; l[i] = 0.f;
#pragma unroll
            for (int d = 0; d < 4; d++) o[i][d] = 0.f;
        }

        for (int k0 = 0; k0 < kn; k0 += 32) {
            const int cnk = min(32, kn - k0);
            __syncthreads();
            // load K transposed + V (zero-pad V rows >= cnk)
            for (int task = tid; task < 512; task += 256) {
                int row = task >> 4, slot = task & 15;
                float* dv = &vsh[row * QS + slot * 4];
                if (row < cnk) {
                    int t = klist[ks + k0 + row];
                    float4 k4 = *reinterpret_cast<const float4*>(Kp + (size_t)t * EMB + slot * 4);
                    ksh[(slot * 4 + 0) * KS + row] = k4.x;
                    ksh[(slot * 4 + 1) * KS + row] = k4.y;
                    ksh[(slot * 4 + 2) * KS + row] = k4.z;
                    ksh[(slot * 4 + 3) * KS + row] = k4.w;
                    float4 v4 = *reinterpret_cast<const float4*>(Vp + (size_t)t * EMB + slot * 4);
                    dv[0] = v4.x; dv[1] = v4.y; dv[2] = v4.z; dv[3] = v4.w;
                } else {
                    dv[0] = 0.f; dv[1] = 0.f; dv[2] = 0.f; dv[3] = 0.f;
                }
            }
            __syncthreads();

            // S = Q @ K^T  (2x2 per thread)
            float s00 = 0.f, s01 = 0.f, s10 = 0.f, s11 = 0.f;
            const float* q0p = &qsh[(ty * 2 + 0) * QS];
            const float* q1p = &qsh[(ty * 2 + 1) * QS];
#pragma unroll 8
            for (int k = 0; k < 64; k++) {
                float a0 = q0p[k];
                float a1 = q1p[k];
                float b0 = ksh[k * KS + tx * 2 + 0];
                float b1 = ksh[k * KS + tx * 2 + 1];
                s00 += a0 * b0; s01 += a0 * b1;
                s10 += a1 * b0; s11 += a1 * b1;
            }
            const bool c0 = (tx * 2 + 0) < cnk;
            const bool c1 = (tx * 2 + 1) < cnk;
            float s4[2][2];
            s4[0][0] = c0 ? s00 * 0.125f : -INFINITY;
            s4[0][1] = c1 ? s01 * 0.125f : -INFINITY;
            s4[1][0] = c0 ? s10 * 0.125f : -INFINITY;
            s4[1][1] = c1 ? s11 * 0.125f : -INFINITY;

            // online softmax per q-row (16-lane row group)
#pragma unroll
            for (int i = 0; i < 2; i++) {
                float cm = fmaxf(s4[i][0], s4[i][1]);
#pragma unroll
                for (int off = 1; off < 16; off <<= 1)
                    cm = fmaxf(cm, __shfl_xor_sync(FULLMASK, cm, off));
                float mn = fmaxf(m[i], cm);
                float corr = __expf(m[i] - mn);
                m[i] = mn;
                float w0 = __expf(s4[i][0] - mn);
                float w1 = __expf(s4[i][1] - mn);
                s4[i][0] = w0; s4[i][1] = w1;
                float ps = w0 + w1;
#pragma unroll
                for (int off = 1; off < 16; off <<= 1)
                    ps += __shfl_xor_sync(FULLMASK, ps, off);
                l[i] = l[i] * corr + ps;
#pragma unroll
                for (int d = 0; d < 4; d++) o[i][d] *= corr;
            }
            // stage P
#pragma unroll
            for (int i = 0; i < 2; i++) {
                psh[(ty * 2 + i) * KS + tx * 2 + 0] = s4[i][0];
                psh[(ty * 2 + i) * KS + tx * 2 + 1] = s4[i][1];
            }
            __syncthreads();
            // O += P @ V
            const float* p0 = &psh[(ty * 2 + 0) * KS];
            const float* p1 = &psh[(ty * 2 + 1) * KS];
#pragma unroll 8
            for (int j = 0; j < 32; j++) {
                float pv0 = p0[j];
                float pv1 = p1[j];
                float4 vv = *reinterpret_cast<const float4*>(&vsh[j * QS + tx * 4]);
                o[0][0] += pv0 * vv.x; o[0][1] += pv0 * vv.y;
                o[0][2] += pv0 * vv.z; o[0][3] += pv0 * vv.w;
                o[1][0] += pv1 * vv.x; o[1][1] += pv1 * vv.y;
                o[1][2] += pv1 * vv.z; o[1][3] += pv1 * vv.w;
            }
        }

#pragma unroll
        for (int i = 0; i < 2; i++) {
            int row = ty * 2 + i;
            if (row < cq) {
                float inv = 1.f / l[i];
                int t = qid[row];
                float4 v;
                v.x = o[i][0] * inv; v.y = o[i][1] * inv;
                v.z = o[i][2] * inv; v.w = o[i][3] * inv;
                *reinterpret_cast<float4*>(Op + (size_t)t * EMB + tx * 4) = v;
            }
        }
    }
}

// ---------------------------------------------------------------------------
// Kernel 5: output projection, fused hash-average + transpose store.
// ---------------------------------------------------------------------------
__global__ __launch_bounds__(256, 2) void gemm_out(const float* __restrict__ W,
                                                   const float* __restrict__ bias,
                                                   float* __restrict__ out)
{
    extern __shared__ float sm[];
    float* A2 = sm;
    float* Bx = sm + 2 * 16 * AS2_STRIDE;

    const int tid = threadIdx.x;
    const int bn = blockIdx.x;
    const int bm = blockIdx.y;
    const int tx = tid & 15, ty = tid >> 4;

    const int rr = tid >> 1;
    const int kb = (tid & 1) * 8;
    const int r = bm * 128 + rr;
    const float* A0 = &g_att[0][(size_t)r * EMB + kb];
    const float* A1 = &g_att[1][(size_t)r * EMB + kb];
    const float* Bptr = W + (size_t)(bn * 128 + rr) * EMB + kb;

    float2 acc[8][4];
#pragma unroll
    for (int i = 0; i < 8; i++)
#pragma unroll
        for (int p = 0; p < 4; p++) acc[i][p] = make_float2(0.f, 0.f);

    float4 ra0, ra1, rb0, rb1;
    {
        float4 x0 = *reinterpret_cast<const float4*>(A0);
        float4 y0 = *reinterpret_cast<const float4*>(A1);
        float4 x1 = *reinterpret_cast<const float4*>(A0 + 4);
        float4 y1 = *reinterpret_cast<const float4*>(A1 + 4);
        ra0 = make_float4(0.5f * (x0.x + y0.x), 0.5f * (x0.y + y0.y), 0.5f * (x0.z + y0.z), 0.5f * (x0.w + y0.w));
        ra1 = make_float4(0.5f * (x1.x + y1.x), 0.5f * (x1.y + y1.y), 0.5f * (x1.z + y1.z), 0.5f * (x1.w + y1.w));
        rb0 = *reinterpret_cast<const float4*>(Bptr);
        rb1 = *reinterpret_cast<const float4*>(Bptr + 4);
        float va[8] = {ra0.x, ra0.y, ra0.z, ra0.w, ra1.x, ra1.y, ra1.z, ra1.w};
        float vb[8] = {rb0.x, rb0.y, rb0.z, rb0.w, rb1.x, rb1.y, rb1.z, rb1.w};
#pragma unroll
        for (int c = 0; c < 8; c++) {
            float* pa = A2 + (kb + c) * AS2_STRIDE + 2 * rr;
            pa[0] = va[c]; pa[1] = va[c];
            Bx[(kb + c) * BSX_STRIDE + rr] = vb[c];
        }
    }
    __syncthreads();

    const int NS = EMB / 16;
    for (int s = 0; s < NS; s++) {
        const int cur = s & 1;
        if (s + 1 < NS) {
            const int o = (s + 1) * 16;
            float4 x0 = *reinterpret_cast<const float4*>(A0 + o);
            float4 y0 = *reinterpret_cast<const float4*>(A1 + o);
            float4 x1 = *reinterpret_cast<const float4*>(A0 + o + 4);
            float4 y1 = *reinterpret_cast<const float4*>(A1 + o + 4);
            ra0 = make_float4(0.5f * (x0.x + y0.x), 0.5f * (x0.y + y0.y), 0.5f * (x0.z + y0.z), 0.5f * (x0.w + y0.w));
            ra1 = make_float4(0.5f * (x1.x + y1.x), 0.5f * (x1.y + y1.y), 0.5f * (x1.z + y1.z), 0.5f * (x1.w + y1.w));
            rb0 = *reinterpret_cast<const float4*>(Bptr + o);
            rb1 = *reinterpret_cast<const float4*>(Bptr + o + 4);
        }
        tile_fma2(A2 + cur * 16 * AS2_STRIDE, Bx + cur * 16 * BSX_STRIDE, acc, tx, ty);
        if (s + 1 < NS) {
            __syncthreads();
            const int nxt = cur ^ 1;
            float va[8] = {ra0.x, ra0.y, ra0.z, ra0.w, ra1.x, ra1.y, ra1.z, ra1.w};
            float vb[8] = {rb0.x, rb0.y, rb0.z, rb0.w, rb1.x, rb1.y, rb1.z, rb1.w};
#pragma unroll
            for (int c = 0; c < 8; c++) {
                float* pa = A2 + (nxt * 16 + kb + c) * AS2_STRIDE + 2 * rr;
                pa[0] = va[c]; pa[1] = va[c];
                Bx[(nxt * 16 + kb + c) * BSX_STRIDE + rr] = vb[c];
            }
            __syncthreads();
        }
    }

    float2 bb2[4];
#pragma unroll
    for (int p = 0; p < 4; p++)
        bb2[p] = *reinterpret_cast<const float2*>(bias + bn * 128 + p * 32 + tx * 2);
#pragma unroll
    for (int i = 0; i < 8; i++) {
        int ro = bm * 128 + ty * 8 + i;           // (nb, nt) flat
        int g = (ro & 2047) * B_SZ + (ro >> 11);  // -> (nt, nb) flat
        float* op = out + (size_t)g * EMB + bn * 128;
#pragma unroll
        for (int p = 0; p < 4; p++) {
            float2 v = acc[i][p];
            v.x += bb2[p].x; v.y += bb2[p].y;
            *reinterpret_cast<float2*>(op + p * 32 + tx * 2) = v;
        }
    }
}

// ---------------------------------------------------------------------------
extern "C" void kernel_launch(void* const* d_in, const int* in_sizes, int n_in,
                              void* d_out, int out_size)
{
    (void)in_sizes; (void)n_in; (void)out_size;
    const float* query = (const float*)d_in[0];
    const float* key   = (const float*)d_in[1];
    const float* value = (const float*)d_in[2];
    const float* Wq = (const float*)d_in[3];
    const float* bq = (const float*)d_in[4];
    const float* Wk = (const float*)d_in[5];
    const float* bk = (const float*)d_in[6];
    const float* Wv = (const float*)d_in[7];
    const float* bv = (const float*)d_in[8];
    const float* Wo = (const float*)d_in[9];
    const float* bo = (const float*)d_in[10];
    const float* lshW = (const float*)d_in[11];
    const float* lshb = (const float*)d_in[12];
    float* out = (float*)d_out;

    cudaFuncSetAttribute(gemm_qkv, cudaFuncAttributeMaxDynamicSharedMemorySize, QKV_SMEM);
    cudaFuncSetAttribute(gemm_out, cudaFuncAttributeMaxDynamicSharedMemorySize, QKV_SMEM);

    gemm_qkv<<<dim3(EMB / 128, ROWS / 128, 3), 256, QKV_SMEM>>>(query, key, value,
                                                                Wq, Wk, Wv, bq, bk, bv);
    hash_gemm<<<dim3(512, 2), 256>>>(lshW, lshb);
    bucketize_kernel<<<32, 256>>>();
    attn_bucket_kernel<<<dim3(64, 32), 256>>>();
    gemm_out<<<dim3(EMB / 128, ROWS / 128), 256, QKV_SMEM>>>(Wo, bo, out);
}